// round 3
// baseline (speedup 1.0000x reference)
#include <cuda_runtime.h>
#include <cuda_bf16.h>

// Distance_26379689132772: dense radius_graph over N=8192 atoms, 128 atoms/mol.
// Output layout (f32): [0, N*N)       edge_weight (row-major [i,j])
//                      [N*N, 2*N*N)  mask as 0.0/1.0
//
// Pure HBM-store-bound (512 MB written). Grid-stride persistent shape +
// streaming stores to approach the write-bandwidth ceiling.

#define NATOMS 8192
#define CUT_HI 5.0f
#define QUADS  (NATOMS * NATOMS / 4)   // 16,777,216 float4 per plane

__device__ __forceinline__ void compute_quad(const float* __restrict__ pos,
                                             const int*   __restrict__ batch,
                                             unsigned idx,
                                             float4& ew, float4& mk)
{
    int i = (int)(idx >> 11);            // idx / 2048
    int j = (int)((idx & 2047u) << 2);   // 4*(idx % 2048)

    ew = make_float4(0.f, 0.f, 0.f, 0.f);
    mk = make_float4(0.f, 0.f, 0.f, 0.f);

    int bi = __ldg(batch + i);
    int bj = __ldg(batch + j);           // j..j+3 share a 128-block (j%4==0)

    if (bi == bj) {
        float xi = __ldg(pos + 3 * i + 0);
        float yi = __ldg(pos + 3 * i + 1);
        float zi = __ldg(pos + 3 * i + 2);
        float sqi = xi * xi + yi * yi + zi * zi;

        float w[4], m[4];
        #pragma unroll
        for (int k = 0; k < 4; k++) {
            int jj = j + k;
            float xj = __ldg(pos + 3 * jj + 0);
            float yj = __ldg(pos + 3 * jj + 1);
            float zj = __ldg(pos + 3 * jj + 2);
            float sqj = xj * xj + yj * yj + zj * zj;
            float d2 = sqi + sqj - 2.0f * (xi * xj + yi * yj + zi * zj);
            d2 = fmaxf(d2, 0.0f);
            float d = (d2 > 0.0f) ? sqrtf(d2) : 0.0f;
            bool mask = (i != jj) && (d <= CUT_HI);
            w[k] = mask ? d : 0.0f;
            m[k] = mask ? 1.0f : 0.0f;
        }
        ew = make_float4(w[0], w[1], w[2], w[3]);
        mk = make_float4(m[0], m[1], m[2], m[3]);
    }
}

__global__ __launch_bounds__(256)
void dist_kernel(const float* __restrict__ pos,
                 const int*   __restrict__ batch,
                 float*       __restrict__ out)
{
    float4* __restrict__ ow = (float4*)out;          // edge_weight plane
    float4* __restrict__ om = ow + QUADS;            // mask plane
    const unsigned stride = gridDim.x * 256u;
    unsigned idx = blockIdx.x * 256u + threadIdx.x;

    // Two quads per loop iteration: 4 STG.128 in flight per warp per trip.
    for (; idx + stride < QUADS; idx += 2u * stride) {
        float4 ew0, mk0, ew1, mk1;
        compute_quad(pos, batch, idx,          ew0, mk0);
        compute_quad(pos, batch, idx + stride, ew1, mk1);
        __stcs(ow + idx,          ew0);
        __stcs(ow + idx + stride, ew1);
        __stcs(om + idx,          mk0);
        __stcs(om + idx + stride, mk1);
    }
    if (idx < QUADS) {
        float4 ew, mk;
        compute_quad(pos, batch, idx, ew, mk);
        __stcs(ow + idx, ew);
        __stcs(om + idx, mk);
    }
}

extern "C" void kernel_launch(void* const* d_in, const int* in_sizes, int n_in,
                              void* d_out, int out_size)
{
    const float* pos   = (const float*)d_in[0];
    const int*   batch = (const int*)d_in[1];
    float*       out   = (float*)d_out;

    // Persistent-ish shape: 148 SMs * 16 blocks, 256 threads each.
    // Each thread handles ~28 quads via grid stride.
    dist_kernel<<<148 * 16, 256>>>(pos, batch, out);
}

// round 4
// speedup vs baseline: 1.1316x; 1.1316x over previous
#include <cuda_runtime.h>
#include <cuda_bf16.h>

// Distance_26379689132772: dense radius_graph over N=8192 atoms, 128 atoms/mol.
// Output layout (f32): [0, N*N)       edge_weight (row-major [i,j])
//                      [N*N, 2*N*N)  mask as 0.0/1.0
//
// Pure HBM-store-bound (512 MB written). Flat launch (R1 structure, proven
// 77.8us / 6.36 TB/s), with 2 quads per thread via block-local stride so each
// STG.128 stays fully coalesced and each thread has 4 stores in flight.

#define NATOMS 8192
#define CUT_HI 5.0f
#define QUADS  (NATOMS * NATOMS / 4)   // 16,777,216 float4 per plane

__device__ __forceinline__ void compute_quad(const float* __restrict__ pos,
                                             const int*   __restrict__ batch,
                                             unsigned idx,
                                             float4& ew, float4& mk)
{
    int i = (int)(idx >> 11);            // idx / 2048
    int j = (int)((idx & 2047u) << 2);   // 4*(idx % 2048)

    ew = make_float4(0.f, 0.f, 0.f, 0.f);
    mk = make_float4(0.f, 0.f, 0.f, 0.f);

    int bi = __ldg(batch + i);
    int bj = __ldg(batch + j);           // j..j+3 share a 128-block (j%4==0)

    if (bi == bj) {
        float xi = __ldg(pos + 3 * i + 0);
        float yi = __ldg(pos + 3 * i + 1);
        float zi = __ldg(pos + 3 * i + 2);
        float sqi = xi * xi + yi * yi + zi * zi;

        float w[4], m[4];
        #pragma unroll
        for (int k = 0; k < 4; k++) {
            int jj = j + k;
            float xj = __ldg(pos + 3 * jj + 0);
            float yj = __ldg(pos + 3 * jj + 1);
            float zj = __ldg(pos + 3 * jj + 2);
            float sqj = xj * xj + yj * yj + zj * zj;
            float d2 = sqi + sqj - 2.0f * (xi * xj + yi * yj + zi * zj);
            d2 = fmaxf(d2, 0.0f);
            float d = (d2 > 0.0f) ? sqrtf(d2) : 0.0f;
            bool mask = (i != jj) && (d <= CUT_HI);
            w[k] = mask ? d : 0.0f;
            m[k] = mask ? 1.0f : 0.0f;
        }
        ew = make_float4(w[0], w[1], w[2], w[3]);
        mk = make_float4(m[0], m[1], m[2], m[3]);
    }
}

__global__ __launch_bounds__(256)
void dist_kernel(const float* __restrict__ pos,
                 const int*   __restrict__ batch,
                 float*       __restrict__ out)
{
    float4* __restrict__ ow = (float4*)out;   // edge_weight plane
    float4* __restrict__ om = ow + QUADS;     // mask plane

    // Block covers 512 consecutive quads; thread t handles t and t+256.
    unsigned base = blockIdx.x * 512u + threadIdx.x;
    unsigned q0 = base;
    unsigned q1 = base + 256u;

    float4 ew0, mk0, ew1, mk1;
    compute_quad(pos, batch, q0, ew0, mk0);
    compute_quad(pos, batch, q1, ew1, mk1);

    ow[q0] = ew0;
    ow[q1] = ew1;
    om[q0] = mk0;
    om[q1] = mk1;
}

extern "C" void kernel_launch(void* const* d_in, const int* in_sizes, int n_in,
                              void* d_out, int out_size)
{
    const float* pos   = (const float*)d_in[0];
    const int*   batch = (const int*)d_in[1];
    float*       out   = (float*)d_out;

    // QUADS / 512 = 32768 blocks, 256 threads each, 2 quads per thread.
    dist_kernel<<<QUADS / 512, 256>>>(pos, batch, out);
}